// round 8
// baseline (speedup 1.0000x reference)
#include <cuda_runtime.h>
#include <cuda_bf16.h>
#include <math.h>
#include <stddef.h>
#include <stdint.h>

// Problem constants
#define NB 2
#define NT 2048
#define ND 1024
#define NH 8
#define KDIM 128
#define VDIM 256
#define NTOK (NB*NT)       // 4096
#define KEYDIM 1024
#define VALDIM 2048
#define NPROJ 6144         // q(1024) | k(1024) | v(2048) | g(2048)

// ---------------------------------------------------------------------------
// Scratch (static device globals; no allocation in kernel_launch)
// ---------------------------------------------------------------------------
__device__ float g_qpre[(size_t)NTOK*KEYDIM];
__device__ float g_kpre[(size_t)NTOK*KEYDIM];
__device__ float g_vpre[(size_t)NTOK*VALDIM];
__device__ float g_q   [(size_t)NTOK*KEYDIM];
__device__ float g_k   [(size_t)NTOK*KEYDIM];
__device__ float g_v   [(size_t)NTOK*VALDIM];
__device__ float g_gate[(size_t)NTOK*VALDIM];
__device__ float g_o   [(size_t)NTOK*VALDIM];
__device__ float g_apre[(size_t)NTOK*NH];
__device__ float g_bpre[(size_t)NTOK*NH];
__device__ float g_alpha[(size_t)NTOK*NH];
__device__ float g_beta [(size_t)NTOK*NH];
__device__ float g_wtab [(size_t)16*ND];

// bf16 hi/lo split scratch for tensor-core GEMMs
__device__ __align__(16) __nv_bfloat16 g_xh[(size_t)NTOK*ND];
__device__ __align__(16) __nv_bfloat16 g_xl[(size_t)NTOK*ND];
__device__ __align__(16) __nv_bfloat16 g_oh[(size_t)NTOK*VALDIM];
__device__ __align__(16) __nv_bfloat16 g_ol[(size_t)NTOK*VALDIM];
// transposed weights [N,K] bf16 hi/lo; sized for fused proj (6144x1024)
__device__ __align__(16) __nv_bfloat16 g_wth[(size_t)NPROJ*ND];
__device__ __align__(16) __nv_bfloat16 g_wtl[(size_t)NPROJ*ND];

// ---------------------------------------------------------------------------
// helpers
// ---------------------------------------------------------------------------
__device__ __forceinline__ uint32_t smem_u32(const void* p) {
    uint32_t a;
    asm("{ .reg .u64 t; cvta.to.shared.u64 t, %1; cvt.u32.u64 %0, t; }"
        : "=r"(a) : "l"(p));
    return a;
}

#define CP_ASYNC16(dst, src) \
    asm volatile("cp.async.cg.shared.global [%0], [%1], 16;" :: "r"(dst), "l"(src))
#define CP_COMMIT() asm volatile("cp.async.commit_group;")
#define CP_WAIT(n)  asm volatile("cp.async.wait_group %0;" :: "n"(n))

#define LDMX4(r, addr) \
    asm volatile("ldmatrix.sync.aligned.m8n8.x4.shared.b16 {%0,%1,%2,%3}, [%4];" \
        : "=r"((r)[0]), "=r"((r)[1]), "=r"((r)[2]), "=r"((r)[3]) : "r"(addr))

#define MMA_BF16(c, a, b) \
    asm volatile("mma.sync.aligned.m16n8k16.row.col.f32.bf16.bf16.f32 " \
        "{%0,%1,%2,%3}, {%4,%5,%6,%7}, {%8,%9}, {%0,%1,%2,%3};" \
        : "+f"((c)[0]), "+f"((c)[1]), "+f"((c)[2]), "+f"((c)[3]) \
        : "r"((a)[0]), "r"((a)[1]), "r"((a)[2]), "r"((a)[3]), \
          "r"((b)[0]), "r"((b)[1]))

// ---------------------------------------------------------------------------
// Tensor-core GEMM (legacy mma.sync, base sm_100 ISA):
//   C = (Ah+Al)[M,K] x (Bh+Bl)[N,K]^T   (bf16 hi/lo, 3 products)
// CTA tile 128x128, BK=32, 512 threads (16 warps = 4m x 4n, warp tile 32x32),
// cp.async 3-stage pipeline, 80B smem row stride (ldmatrix conflict-free).
// 16 warps/SM (vs 8 before) to feed the tensor pipe (was 50.9% busy, occ 12.5%).
// FUSED=1: epilogue routes 128-col tiles to 4 destination buffers.
// ---------------------------------------------------------------------------
#define TILE_B   10240            // 128 rows * 80 bytes
#define STAGE_B  (4*TILE_B)       // Ah, Al, Bh, Bl
#define GEMM_SMEM (3*STAGE_B)     // 122880 (3-stage)

__device__ __forceinline__ void g2s_chunk(
    uint32_t dbase, const __nv_bfloat16* Ah, const __nv_bfloat16* Al,
    const __nv_bfloat16* Bh, const __nv_bfloat16* Bl,
    int m0, int n0, int k0, int K, int tid)
{
    const __nv_bfloat16* srcs[4] = {
        Ah + (size_t)m0 * K + k0, Al + (size_t)m0 * K + k0,
        Bh + (size_t)n0 * K + k0, Bl + (size_t)n0 * K + k0 };
    const int row = tid >> 2;              // 0..127
    const int q   = tid & 3;               // 16B unit (8 bf16)
#pragma unroll
    for (int t = 0; t < 4; t++) {
        CP_ASYNC16(dbase + t * TILE_B + row * 80 + q * 16,
                   srcs[t] + (size_t)row * K + q * 8);
    }
}

template<int FUSED>
__global__ __launch_bounds__(512, 1) void gemm_mma(
    const __nv_bfloat16* __restrict__ Ah, const __nv_bfloat16* __restrict__ Al,
    const __nv_bfloat16* __restrict__ Bh, const __nv_bfloat16* __restrict__ Bl,
    float* __restrict__ C0, float* __restrict__ C1,
    float* __restrict__ C2, float* __restrict__ C3,
    int Nsingle, int K)
{
    extern __shared__ __align__(16) char smem[];
    const uint32_t sbase = smem_u32(smem);
    const int tid  = threadIdx.x;
    const int wid  = tid >> 5, lane = tid & 31;
    const int wm   = wid >> 2, wn = wid & 3;      // 4m x 4n warps
    const int m0   = blockIdx.y * 128;
    const int n0   = blockIdx.x * 128;

    const int mat = lane >> 3;             // ldmatrix quadrant
    const int r   = lane & 7;

    float acc[2][4][4];
#pragma unroll
    for (int f = 0; f < 2; f++)
#pragma unroll
        for (int p = 0; p < 4; p++)
#pragma unroll
            for (int j = 0; j < 4; j++) acc[f][p][j] = 0.f;

    const int nc = K >> 5;

    // prologue: chunks 0,1 -> stages 0,1
    g2s_chunk(sbase, Ah, Al, Bh, Bl, m0, n0, 0, K, tid);
    CP_COMMIT();
    if (nc > 1) {
        g2s_chunk(sbase + STAGE_B, Ah, Al, Bh, Bl, m0, n0, 32, K, tid);
        CP_COMMIT();
    }

    for (int c = 0; c < nc; c++) {
        if (c + 2 < nc) {
            g2s_chunk(sbase + ((c + 2) % 3) * STAGE_B,
                      Ah, Al, Bh, Bl, m0, n0, (c + 2) << 5, K, tid);
            CP_COMMIT();
            CP_WAIT(2);
        } else if (c + 1 < nc) {
            CP_WAIT(1);
        } else {
            CP_WAIT(0);
        }
        __syncthreads();

        const uint32_t ab  = sbase + (c % 3) * STAGE_B;          // Ah tile
        const uint32_t alb = ab + TILE_B;
        const uint32_t bhb = ab + 2 * TILE_B;
        const uint32_t blb = ab + 3 * TILE_B;

#pragma unroll
        for (int ks = 0; ks < 2; ks++) {
            uint32_t fa_h[2][4], fa_l[2][4];
#pragma unroll
            for (int f = 0; f < 2; f++) {
                int row  = wm * 32 + f * 16 + ((mat & 1) << 3) + r;
                int kcol = ks * 16 + ((mat >> 1) << 3);
                uint32_t off = row * 80 + kcol * 2;
                LDMX4(fa_h[f], ab  + off);
                LDMX4(fa_l[f], alb + off);
            }
            uint32_t fb_h[4][2], fb_l[4][2];
#pragma unroll
            for (int pp = 0; pp < 2; pp++) {
                int row  = wn * 32 + pp * 16 + ((mat >> 1) << 3) + r;
                int kcol = ks * 16 + ((mat & 1) << 3);
                uint32_t off = row * 80 + kcol * 2;
                uint32_t t4[4];
                LDMX4(t4, bhb + off);
                fb_h[pp*2][0] = t4[0]; fb_h[pp*2][1] = t4[1];
                fb_h[pp*2+1][0] = t4[2]; fb_h[pp*2+1][1] = t4[3];
                LDMX4(t4, blb + off);
                fb_l[pp*2][0] = t4[0]; fb_l[pp*2][1] = t4[1];
                fb_l[pp*2+1][0] = t4[2]; fb_l[pp*2+1][1] = t4[3];
            }
#pragma unroll
            for (int f = 0; f < 2; f++)
#pragma unroll
                for (int p = 0; p < 4; p++) {
                    MMA_BF16(acc[f][p], fa_h[f], fb_h[p]);
                    MMA_BF16(acc[f][p], fa_h[f], fb_l[p]);
                    MMA_BF16(acc[f][p], fa_l[f], fb_h[p]);
                }
        }
        __syncthreads();
    }

    // epilogue: pick destination buffer / ld / column base
    float* Cd; int ldc, cb;
    if (FUSED) {
        if (n0 < 1024)      { Cd = C0; ldc = 1024; cb = n0; }
        else if (n0 < 2048) { Cd = C1; ldc = 1024; cb = n0 - 1024; }
        else if (n0 < 4096) { Cd = C2; ldc = 2048; cb = n0 - 2048; }
        else                { Cd = C3; ldc = 2048; cb = n0 - 4096; }
    } else {
        Cd = C0; ldc = Nsingle; cb = n0;
    }
#pragma unroll
    for (int f = 0; f < 2; f++) {
        int row0 = m0 + wm * 32 + f * 16 + (lane >> 2);
#pragma unroll
        for (int p = 0; p < 4; p++) {
            int col = cb + wn * 32 + p * 8 + (lane & 3) * 2;
            *(float2*)&Cd[(size_t)row0 * ldc + col] =
                make_float2(acc[f][p][0], acc[f][p][1]);
            *(float2*)&Cd[(size_t)(row0 + 8) * ldc + col] =
                make_float2(acc[f][p][2], acc[f][p][3]);
        }
    }
}

// ---------------------------------------------------------------------------
// fp32 -> bf16 hi/lo elementwise split
// ---------------------------------------------------------------------------
__global__ void cvt_hilo(const float* __restrict__ x,
                         __nv_bfloat16* __restrict__ hi,
                         __nv_bfloat16* __restrict__ lo, int n)
{
    int i = blockIdx.x * blockDim.x + threadIdx.x;
    if (i >= n) return;
    float v = x[i];
    __nv_bfloat16 h = __float2bfloat16(v);
    hi[i] = h;
    lo[i] = __float2bfloat16(v - __bfloat162float(h));
}

// W[K,N] fp32 -> Wt[N,K] bf16 hi/lo (transpose + split); single-weight form
__global__ void transpose_cvt(const float* __restrict__ W,
                              __nv_bfloat16* __restrict__ Th,
                              __nv_bfloat16* __restrict__ Tl, int K, int N)
{
    __shared__ float tile[32][33];
    int kb = blockIdx.y * 32, nb = blockIdx.x * 32;
    int tx = threadIdx.x, ty = threadIdx.y;
#pragma unroll
    for (int i = ty; i < 32; i += 8)
        tile[i][tx] = W[(size_t)(kb + i) * N + nb + tx];
    __syncthreads();
#pragma unroll
    for (int i = ty; i < 32; i += 8) {
        float v = tile[tx][i];                     // = W[kb+tx][nb+i]
        __nv_bfloat16 h = __float2bfloat16(v);
        size_t oidx = (size_t)(nb + i) * K + kb + tx;
        Th[oidx] = h;
        Tl[oidx] = __float2bfloat16(v - __bfloat162float(h));
    }
}

// Fused transpose of Wq|Wk|Wv|Wg into the [6144][1024] buffer (one launch).
__global__ void transpose_all(const float* __restrict__ Wq,
                              const float* __restrict__ Wk,
                              const float* __restrict__ Wv,
                              const float* __restrict__ Wg,
                              __nv_bfloat16* __restrict__ Th,
                              __nv_bfloat16* __restrict__ Tl)
{
    __shared__ float tile[32][33];
    int bid = blockIdx.x;
    const float* W; int N; size_t off;
    if (bid < 1024)      { W = Wq; N = KEYDIM; off = 0;                  }
    else if (bid < 2048) { W = Wk; N = KEYDIM; off = (size_t)1024*ND; bid -= 1024; }
    else if (bid < 4096) { W = Wv; N = VALDIM; off = (size_t)2048*ND; bid -= 2048; }
    else                 { W = Wg; N = VALDIM; off = (size_t)4096*ND; bid -= 4096; }
    int nblk = N / 32;
    int nb = (bid % nblk) * 32;
    int kb = (bid / nblk) * 32;
    int tx = threadIdx.x, ty = threadIdx.y;
#pragma unroll
    for (int i = ty; i < 32; i += 8)
        tile[i][tx] = W[(size_t)(kb + i) * N + nb + tx];
    __syncthreads();
#pragma unroll
    for (int i = ty; i < 32; i += 8) {
        float v = tile[tx][i];
        __nv_bfloat16 h = __float2bfloat16(v);
        size_t oidx = off + (size_t)(nb + i) * ND + kb + tx;
        Th[oidx] = h;
        Tl[oidx] = __float2bfloat16(v - __bfloat162float(h));
    }
}

// ---------------------------------------------------------------------------
// Wa/Wb fused: pre-transpose to Wt[16][1024], then warp-per-token dot.
// ---------------------------------------------------------------------------
__global__ void build_wtab(const float* __restrict__ Wa,
                           const float* __restrict__ Wb,
                           float* __restrict__ Wt)
{
    int i = blockIdx.x * blockDim.x + threadIdx.x;
    if (i >= 16 * ND) return;
    int o = i / ND, k = i - o * ND;
    Wt[i] = (o < 8) ? Wa[(size_t)k * NH + o] : Wb[(size_t)k * NH + (o - 8)];
}

__global__ __launch_bounds__(256) void abproj_kernel(
    const float* __restrict__ x, const float* __restrict__ Wt,
    float* __restrict__ apre, float* __restrict__ bpre)
{
    int warp = (blockIdx.x * blockDim.x + threadIdx.x) >> 5;   // token
    int lane = threadIdx.x & 31;
    if (warp >= NTOK) return;
    const float* xr = x + (size_t)warp * ND;

    float acc[16];
#pragma unroll
    for (int o = 0; o < 16; o++) acc[o] = 0.f;

    for (int k0 = 0; k0 < ND; k0 += 32) {
        float xv = xr[k0 + lane];
#pragma unroll
        for (int o = 0; o < 16; o++)
            acc[o] += xv * Wt[o * ND + k0 + lane];
    }
#pragma unroll
    for (int o = 0; o < 16; o++) {
#pragma unroll
        for (int off = 16; off > 0; off >>= 1)
            acc[o] += __shfl_xor_sync(0xffffffffu, acc[o], off);
    }
    if (lane == 0) {
#pragma unroll
        for (int o = 0; o < 8; o++) {
            apre[(size_t)warp * 8 + o] = acc[o];
            bpre[(size_t)warp * 8 + o] = acc[8 + o];
        }
    }
}

// ---------------------------------------------------------------------------
// alpha/beta epilogue
// ---------------------------------------------------------------------------
__global__ void ab_kernel(const float* __restrict__ apre,
                          const float* __restrict__ bpre,
                          const float* __restrict__ A_log,
                          const float* __restrict__ dt_bias,
                          float* __restrict__ alpha,
                          float* __restrict__ beta)
{
    int i = blockIdx.x * blockDim.x + threadIdx.x;
    if (i >= NTOK*NH) return;
    int h = i & (NH-1);
    float xv = apre[i] + dt_bias[h];
    float sp = (xv > 20.f) ? xv : log1pf(expf(xv));
    alpha[i] = expf(-expf(A_log[h]) * sp);
    float bv = bpre[i];
    beta[i] = 2.f / (1.f + expf(-bv));
}

// ---------------------------------------------------------------------------
// Causal depthwise conv (KS=4) + SiLU (+ optional per-head l2norm)
// ---------------------------------------------------------------------------
template<int C, bool NORM>
__global__ void conv_silu_kernel(const float* __restrict__ xin,
                                 const float* __restrict__ w,
                                 float* __restrict__ out)
{
    int t  = blockIdx.x;
    int tt = t & (NT-1);
    int c4 = threadIdx.x * 4;

    float wc[4][4];
    *(float4*)wc[0] = *(const float4*)&w[(c4+0)*4];
    *(float4*)wc[1] = *(const float4*)&w[(c4+1)*4];
    *(float4*)wc[2] = *(const float4*)&w[(c4+2)*4];
    *(float4*)wc[3] = *(const float4*)&w[(c4+3)*4];

    float acc[4] = {0.f, 0.f, 0.f, 0.f};
#pragma unroll
    for (int j = 0; j < 4; j++) {
        int ts = tt - 3 + j;
        if (ts >= 0) {
            float xr[4];
            *(float4*)xr = *(const float4*)&xin[(size_t)(t-3+j)*C + c4];
#pragma unroll
            for (int ci = 0; ci < 4; ci++)
                acc[ci] += wc[ci][j] * xr[ci];
        }
    }
    float y[4];
#pragma unroll
    for (int ci = 0; ci < 4; ci++) {
        float z = acc[ci];
        y[ci] = z / (1.f + expf(-z));
    }
    if (NORM) {
        float ss = y[0]*y[0] + y[1]*y[1] + y[2]*y[2] + y[3]*y[3];
#pragma unroll
        for (int off = 16; off > 0; off >>= 1)
            ss += __shfl_xor_sync(0xffffffffu, ss, off);
        float n  = sqrtf(ss);
        float sc = 1.f / fmaxf(n, 1e-6f);
#pragma unroll
        for (int ci = 0; ci < 4; ci++) y[ci] *= sc;
    }
    *(float4*)&out[(size_t)t*C + c4] = make_float4(y[0], y[1], y[2], y[3]);
}

// ---------------------------------------------------------------------------
// Gated delta-rule scan. Output reduction deferred out of the serial loop.
// ---------------------------------------------------------------------------
#define SCAN_SMEM (16384 + 16384 + 4096 + 16384 + 128 + 128)

__global__ __launch_bounds__(128, 1) void scan_kernel()
{
    extern __shared__ __align__(16) char ssm[];
    float (*sk)[128]   = (float(*)[128])(ssm);
    float (*sq)[128]   = (float(*)[128])(ssm + 16384);
    float (*sv)[32]    = (float(*)[32]) (ssm + 32768);
    float (*so4)[32][4]= (float(*)[32][4])(ssm + 36864);
    float *sa          = (float*)(ssm + 53248);
    float *sb2         = (float*)(ssm + 53376);

    const int blk = blockIdx.x;
    const int vb  = blk & 7;
    const int h   = (blk >> 3) & 7;
    const int b   = blk >> 6;
    const int vr0 = vb * 32;

    const int tid = threadIdx.x;
    const int row = tid >> 2;
    const int cg  = tid & 3;

    float s[32];
#pragma unroll
    for (int j = 0; j < 32; j++) s[j] = 0.f;

    const size_t tok0 = (size_t)b * NT;

    for (int c0 = 0; c0 < NT; c0 += 32) {
#pragma unroll
        for (int l = 0; l < 8; l++) {
            int id = tid + l*128;
            int st = id >> 5;
            int cq = (id & 31) * 4;
            size_t gidx = (tok0 + c0 + st) * (size_t)KEYDIM + h*KDIM + cq;
            *(float4*)&sk[st][cq] = *(const float4*)&g_k[gidx];
            *(float4*)&sq[st][cq] = *(const float4*)&g_q[gidx];
        }
#pragma unroll
        for (int l = 0; l < 2; l++) {
            int id = tid + l*128;
            int st = id >> 3;
            int vq = (id & 7) * 4;
            *(float4*)&sv[st][vq] =
                *(const float4*)&g_v[(tok0 + c0 + st) * (size_t)VALDIM + h*VDIM + vr0 + vq];
        }
        if (tid < 32)
            sa[tid] = g_alpha[(tok0 + c0 + tid) * NH + h];
        else if (tid < 64)
            sb2[tid-32] = g_beta[(tok0 + c0 + (tid-32)) * NH + h];
        __syncthreads();

        for (int i = 0; i < 32; i++) {
            float a   = sa[i];
            float bb  = sb2[i];
            float abb = a * bb;
            float vv  = sv[i][row];
            float kf[32];
            const float* kr = &sk[i][cg*32];
            const float* qr = &sq[i][cg*32];
#pragma unroll
            for (int j = 0; j < 8; j++)
                *(float4*)&kf[j*4] = *(const float4*)&kr[j*4];
            float r0 = 0.f, r1 = 0.f, r2 = 0.f, r3 = 0.f;
#pragma unroll
            for (int j = 0; j < 8; j++) {
                r0 += s[j*4+0] * kf[j*4+0];
                r1 += s[j*4+1] * kf[j*4+1];
                r2 += s[j*4+2] * kf[j*4+2];
                r3 += s[j*4+3] * kf[j*4+3];
            }
            float r = (r0 + r1) + (r2 + r3);
            r += __shfl_xor_sync(0xffffffffu, r, 1);
            float qf[32];
#pragma unroll
            for (int j = 0; j < 8; j++)
                *(float4*)&qf[j*4] = *(const float4*)&qr[j*4];
            r += __shfl_xor_sync(0xffffffffu, r, 2);
            float c = bb*vv - abb*r;
            float o0 = 0.f, o1 = 0.f, o2 = 0.f, o3 = 0.f;
#pragma unroll
            for (int j = 0; j < 8; j++) {
                s[j*4+0] = a*s[j*4+0] + c*kf[j*4+0]; o0 += s[j*4+0]*qf[j*4+0];
                s[j*4+1] = a*s[j*4+1] + c*kf[j*4+1]; o1 += s[j*4+1]*qf[j*4+1];
                s[j*4+2] = a*s[j*4+2] + c*kf[j*4+2]; o2 += s[j*4+2]*qf[j*4+2];
                s[j*4+3] = a*s[j*4+3] + c*kf[j*4+3]; o3 += s[j*4+3]*qf[j*4+3];
            }
            so4[i][row][cg] = (o0 + o1) + (o2 + o3);
        }
        __syncthreads();

#pragma unroll
        for (int l = 0; l < 8; l++) {
            int id = tid + l*128;
            int st = id >> 5;
            int rr = id & 31;
            float4 p = *(float4*)&so4[st][rr][0];
            g_o[(tok0 + c0 + st) * (size_t)VALDIM + h*VDIM + vr0 + rr] =
                (p.x + p.y) + (p.z + p.w);
        }
    }
}

// ---------------------------------------------------------------------------
// Gating epilogue: writes bf16 hi/lo directly (feeds Wo GEMM)
// ---------------------------------------------------------------------------
__global__ void gate_kernel(const float* __restrict__ o,
                            const float* __restrict__ gate,
                            const float* __restrict__ w,
                            __nv_bfloat16* __restrict__ oh,
                            __nv_bfloat16* __restrict__ ol)
{
    int bh = blockIdx.x;
    size_t base = (size_t)bh * VDIM;
    int tid = threadIdx.x;

    float v  = o[base + tid];
    float ss = v*v;
#pragma unroll
    for (int off = 16; off > 0; off >>= 1)
        ss += __shfl_xor_sync(0xffffffffu, ss, off);
    __shared__ float red[8];
    if ((tid & 31) == 0) red[tid >> 5] = ss;
    __syncthreads();
    float tot = red[0]+red[1]+red[2]+red[3]+red[4]+red[5]+red[6]+red[7];
    float rms = rsqrtf(tot * (1.f/VDIM) + 1e-5f);

    float gv = gate[base + tid];
    float sg = gv / (1.f + expf(-gv));
    float val = v * rms * w[tid] * sg;
    __nv_bfloat16 hi = __float2bfloat16(val);
    oh[base + tid] = hi;
    ol[base + tid] = __float2bfloat16(val - __bfloat162float(hi));
}

// ---------------------------------------------------------------------------
// launch  (gemm_mma<1> stays the 4th launch -> ncu capture slot)
// ---------------------------------------------------------------------------
extern "C" void kernel_launch(void* const* d_in, const int* in_sizes, int n_in,
                              void* d_out, int out_size)
{
    const float* x       = (const float*)d_in[0];
    const float* Wq      = (const float*)d_in[1];
    const float* Wk      = (const float*)d_in[2];
    const float* Wv      = (const float*)d_in[3];
    const float* Wa      = (const float*)d_in[4];
    const float* Wb      = (const float*)d_in[5];
    const float* Wg      = (const float*)d_in[6];
    const float* Wo      = (const float*)d_in[7];
    const float* A_log   = (const float*)d_in[8];
    const float* dt_bias = (const float*)d_in[9];
    const float* conv_q  = (const float*)d_in[10];
    const float* conv_k  = (const float*)d_in[11];
    const float* conv_v  = (const float*)d_in[12];
    const float* o_nw    = (const float*)d_in[13];
    float* out = (float*)d_out;

    float *qpre, *kpre, *vpre, *gatep, *obuf;
    float *apre, *bpre, *alpha, *beta, *wtab;
    __nv_bfloat16 *xh, *xl, *oh, *ol, *wth, *wtl;
    cudaGetSymbolAddress((void**)&qpre,  g_qpre);
    cudaGetSymbolAddress((void**)&kpre,  g_kpre);
    cudaGetSymbolAddress((void**)&vpre,  g_vpre);
    cudaGetSymbolAddress((void**)&gatep, g_gate);
    cudaGetSymbolAddress((void**)&obuf,  g_o);
    cudaGetSymbolAddress((void**)&apre,  g_apre);
    cudaGetSymbolAddress((void**)&bpre,  g_bpre);
    cudaGetSymbolAddress((void**)&alpha, g_alpha);
    cudaGetSymbolAddress((void**)&beta,  g_beta);
    cudaGetSymbolAddress((void**)&wtab,  g_wtab);
    cudaGetSymbolAddress((void**)&xh,    g_xh);
    cudaGetSymbolAddress((void**)&xl,    g_xl);
    cudaGetSymbolAddress((void**)&oh,    g_oh);
    cudaGetSymbolAddress((void**)&ol,    g_ol);
    cudaGetSymbolAddress((void**)&wth,   g_wth);
    cudaGetSymbolAddress((void**)&wtl,   g_wtl);
    float *q, *k, *v;
    cudaGetSymbolAddress((void**)&q, g_q);
    cudaGetSymbolAddress((void**)&k, g_k);
    cudaGetSymbolAddress((void**)&v, g_v);

    cudaFuncSetAttribute(gemm_mma<0>, cudaFuncAttributeMaxDynamicSharedMemorySize,
                         GEMM_SMEM);
    cudaFuncSetAttribute(gemm_mma<1>, cudaFuncAttributeMaxDynamicSharedMemorySize,
                         GEMM_SMEM);
    cudaFuncSetAttribute(scan_kernel, cudaFuncAttributeMaxDynamicSharedMemorySize,
                         SCAN_SMEM);

    dim3 tb(32, 8);

    // 1) split x into bf16 hi/lo
    cvt_hilo<<<(NTOK*ND + 255)/256, 256>>>(x, xh, xl, NTOK*ND);
    // 2) all 4 projection weight transposes in one launch
    transpose_all<<<6144, tb>>>(Wq, Wk, Wv, Wg, wth, wtl);
    // 3) Wa|Wb transpose table
    build_wtab<<<(16*ND + 255)/256, 256>>>(Wa, Wb, wtab);
    // 4) fused projection GEMM  <-- ncu capture slot
    gemm_mma<1><<<dim3(NPROJ/128, NTOK/128), 512, GEMM_SMEM>>>(
        xh, xl, wth, wtl, qpre, kpre, vpre, gatep, 0, ND);

    // Wa/Wb small-N projection
    abproj_kernel<<<(NTOK*32 + 255)/256, 256>>>(x, wtab, apre, bpre);
    ab_kernel<<<(NTOK*NH + 255)/256, 256>>>(apre, bpre, A_log, dt_bias, alpha, beta);

    conv_silu_kernel<KEYDIM, true ><<<NTOK, KEYDIM/4>>>(qpre, conv_q, q);
    conv_silu_kernel<KEYDIM, true ><<<NTOK, KEYDIM/4>>>(kpre, conv_k, k);
    conv_silu_kernel<VALDIM, false><<<NTOK, VALDIM/4>>>(vpre, conv_v, v);

    scan_kernel<<<NB*NH*8, 128, SCAN_SMEM>>>();

    gate_kernel<<<NTOK*NH, VDIM>>>(obuf, gatep, o_nw, oh, ol);

    // Output projection
    transpose_cvt<<<dim3(ND/32, VALDIM/32), tb>>>(Wo, wth, wtl, VALDIM, ND);
    gemm_mma<0><<<dim3(ND/128, NTOK/128), 512, GEMM_SMEM>>>(
        oh, ol, wth, wtl, out, nullptr, nullptr, nullptr, ND, VALDIM);
}

// round 11
// speedup vs baseline: 1.0305x; 1.0305x over previous
#include <cuda_runtime.h>
#include <cuda_bf16.h>
#include <math.h>
#include <stddef.h>
#include <stdint.h>

// Problem constants
#define NB 2
#define NT 2048
#define ND 1024
#define NH 8
#define KDIM 128
#define VDIM 256
#define NTOK (NB*NT)       // 4096
#define KEYDIM 1024
#define VALDIM 2048
#define NPROJ 6144         // q(1024) | k(1024) | v(2048) | g(2048)

// ---------------------------------------------------------------------------
// Scratch (static device globals; no allocation in kernel_launch)
// ---------------------------------------------------------------------------
__device__ float g_qpre[(size_t)NTOK*KEYDIM];
__device__ float g_kpre[(size_t)NTOK*KEYDIM];
__device__ float g_vpre[(size_t)NTOK*VALDIM];
__device__ float g_q   [(size_t)NTOK*KEYDIM];
__device__ float g_k   [(size_t)NTOK*KEYDIM];
__device__ float g_v   [(size_t)NTOK*VALDIM];
__device__ float g_gate[(size_t)NTOK*VALDIM];
__device__ float g_o   [(size_t)NTOK*VALDIM];
__device__ float g_apre[(size_t)NTOK*NH];
__device__ float g_bpre[(size_t)NTOK*NH];
__device__ float g_alpha[(size_t)NTOK*NH];
__device__ float g_beta [(size_t)NTOK*NH];
__device__ float g_wtab [(size_t)16*ND];

// bf16 hi/lo split scratch for tensor-core GEMMs
__device__ __align__(16) __nv_bfloat16 g_xh[(size_t)NTOK*ND];
__device__ __align__(16) __nv_bfloat16 g_xl[(size_t)NTOK*ND];
__device__ __align__(16) __nv_bfloat16 g_oh[(size_t)NTOK*VALDIM];
__device__ __align__(16) __nv_bfloat16 g_ol[(size_t)NTOK*VALDIM];
// transposed weights [N,K] bf16 hi/lo; sized for fused proj (6144x1024)
__device__ __align__(16) __nv_bfloat16 g_wth[(size_t)NPROJ*ND];
__device__ __align__(16) __nv_bfloat16 g_wtl[(size_t)NPROJ*ND];

// ---------------------------------------------------------------------------
// helpers
// ---------------------------------------------------------------------------
__device__ __forceinline__ uint32_t smem_u32(const void* p) {
    uint32_t a;
    asm("{ .reg .u64 t; cvta.to.shared.u64 t, %1; cvt.u32.u64 %0, t; }"
        : "=r"(a) : "l"(p));
    return a;
}

#define CP_ASYNC16(dst, src) \
    asm volatile("cp.async.cg.shared.global [%0], [%1], 16;" :: "r"(dst), "l"(src))
#define CP_COMMIT() asm volatile("cp.async.commit_group;")
#define CP_WAIT(n)  asm volatile("cp.async.wait_group %0;" :: "n"(n))

#define LDMX4(r, addr) \
    asm volatile("ldmatrix.sync.aligned.m8n8.x4.shared.b16 {%0,%1,%2,%3}, [%4];" \
        : "=r"((r)[0]), "=r"((r)[1]), "=r"((r)[2]), "=r"((r)[3]) : "r"(addr))

#define MMA_BF16(c, a, b) \
    asm volatile("mma.sync.aligned.m16n8k16.row.col.f32.bf16.bf16.f32 " \
        "{%0,%1,%2,%3}, {%4,%5,%6,%7}, {%8,%9}, {%0,%1,%2,%3};" \
        : "+f"((c)[0]), "+f"((c)[1]), "+f"((c)[2]), "+f"((c)[3]) \
        : "r"((a)[0]), "r"((a)[1]), "r"((a)[2]), "r"((a)[3]), \
          "r"((b)[0]), "r"((b)[1]))

// ---------------------------------------------------------------------------
// Tensor-core GEMM (legacy mma.sync, base sm_100 ISA) — R6 best config:
// CTA tile 128x128, BK=32, 256 threads (8 warps = 4m x 2n, warp tile 32x64),
// cp.async 3-stage pipeline, 80B smem row stride (ldmatrix conflict-free).
// ---------------------------------------------------------------------------
#define TILE_B   10240            // 128 rows * 80 bytes
#define STAGE_B  (4*TILE_B)       // Ah, Al, Bh, Bl
#define GEMM_SMEM (3*STAGE_B)     // 122880 (3-stage)

__device__ __forceinline__ void g2s_chunk(
    uint32_t dbase, const __nv_bfloat16* Ah, const __nv_bfloat16* Al,
    const __nv_bfloat16* Bh, const __nv_bfloat16* Bl,
    int m0, int n0, int k0, int K, int tid)
{
    const __nv_bfloat16* srcs[4] = {
        Ah + (size_t)m0 * K + k0, Al + (size_t)m0 * K + k0,
        Bh + (size_t)n0 * K + k0, Bl + (size_t)n0 * K + k0 };
#pragma unroll
    for (int t = 0; t < 4; t++) {
        const __nv_bfloat16* src = srcs[t];
        uint32_t db = dbase + t * TILE_B;
#pragma unroll
        for (int l = 0; l < 2; l++) {
            int id  = tid + l * 256;       // 0..511
            int row = id >> 2;             // 0..127
            int q   = id & 3;              // 16B unit (8 bf16)
            CP_ASYNC16(db + row * 80 + q * 16, src + (size_t)row * K + q * 8);
        }
    }
}

template<int FUSED>
__global__ __launch_bounds__(256, 1) void gemm_mma(
    const __nv_bfloat16* __restrict__ Ah, const __nv_bfloat16* __restrict__ Al,
    const __nv_bfloat16* __restrict__ Bh, const __nv_bfloat16* __restrict__ Bl,
    float* __restrict__ C0, float* __restrict__ C1,
    float* __restrict__ C2, float* __restrict__ C3,
    int Nsingle, int K)
{
    extern __shared__ __align__(16) char smem[];
    const uint32_t sbase = smem_u32(smem);
    const int tid  = threadIdx.x;
    const int wid  = tid >> 5, lane = tid & 31;
    const int wm   = wid >> 1, wn = wid & 1;
    const int m0   = blockIdx.y * 128;
    const int n0   = blockIdx.x * 128;

    const int mat = lane >> 3;             // ldmatrix quadrant
    const int r   = lane & 7;

    float acc[2][8][4];
#pragma unroll
    for (int f = 0; f < 2; f++)
#pragma unroll
        for (int p = 0; p < 8; p++)
#pragma unroll
            for (int j = 0; j < 4; j++) acc[f][p][j] = 0.f;

    const int nc = K >> 5;

    // prologue: chunks 0,1 -> stages 0,1
    g2s_chunk(sbase, Ah, Al, Bh, Bl, m0, n0, 0, K, tid);
    CP_COMMIT();
    if (nc > 1) {
        g2s_chunk(sbase + STAGE_B, Ah, Al, Bh, Bl, m0, n0, 32, K, tid);
        CP_COMMIT();
    }

    for (int c = 0; c < nc; c++) {
        if (c + 2 < nc) {
            g2s_chunk(sbase + ((c + 2) % 3) * STAGE_B,
                      Ah, Al, Bh, Bl, m0, n0, (c + 2) << 5, K, tid);
            CP_COMMIT();
            CP_WAIT(2);
        } else if (c + 1 < nc) {
            CP_WAIT(1);
        } else {
            CP_WAIT(0);
        }
        __syncthreads();

        const uint32_t ab  = sbase + (c % 3) * STAGE_B;          // Ah tile
        const uint32_t alb = ab + TILE_B;
        const uint32_t bhb = ab + 2 * TILE_B;
        const uint32_t blb = ab + 3 * TILE_B;

#pragma unroll
        for (int ks = 0; ks < 2; ks++) {
            uint32_t fa_h[2][4], fa_l[2][4];
#pragma unroll
            for (int f = 0; f < 2; f++) {
                int row  = wm * 32 + f * 16 + ((mat & 1) << 3) + r;
                int kcol = ks * 16 + ((mat >> 1) << 3);
                uint32_t off = row * 80 + kcol * 2;
                LDMX4(fa_h[f], ab  + off);
                LDMX4(fa_l[f], alb + off);
            }
            uint32_t fb_h[8][2], fb_l[8][2];
#pragma unroll
            for (int p = 0; p < 4; p++) {
                int row  = wn * 64 + p * 16 + ((mat >> 1) << 3) + r;
                int kcol = ks * 16 + ((mat & 1) << 3);
                uint32_t off = row * 80 + kcol * 2;
                uint32_t t4[4];
                LDMX4(t4, bhb + off);
                fb_h[p*2][0] = t4[0]; fb_h[p*2][1] = t4[1];
                fb_h[p*2+1][0] = t4[2]; fb_h[p*2+1][1] = t4[3];
                LDMX4(t4, blb + off);
                fb_l[p*2][0] = t4[0]; fb_l[p*2][1] = t4[1];
                fb_l[p*2+1][0] = t4[2]; fb_l[p*2+1][1] = t4[3];
            }
#pragma unroll
            for (int f = 0; f < 2; f++)
#pragma unroll
                for (int p = 0; p < 8; p++) {
                    MMA_BF16(acc[f][p], fa_h[f], fb_h[p]);
                    MMA_BF16(acc[f][p], fa_h[f], fb_l[p]);
                    MMA_BF16(acc[f][p], fa_l[f], fb_h[p]);
                }
        }
        __syncthreads();
    }

    // epilogue: pick destination buffer / ld / column base
    float* Cd; int ldc, cb;
    if (FUSED) {
        if (n0 < 1024)      { Cd = C0; ldc = 1024; cb = n0; }
        else if (n0 < 2048) { Cd = C1; ldc = 1024; cb = n0 - 1024; }
        else if (n0 < 4096) { Cd = C2; ldc = 2048; cb = n0 - 2048; }
        else                { Cd = C3; ldc = 2048; cb = n0 - 4096; }
    } else {
        Cd = C0; ldc = Nsingle; cb = n0;
    }
#pragma unroll
    for (int f = 0; f < 2; f++) {
        int row0 = m0 + wm * 32 + f * 16 + (lane >> 2);
#pragma unroll
        for (int p = 0; p < 8; p++) {
            int col = cb + wn * 64 + p * 8 + (lane & 3) * 2;
            *(float2*)&Cd[(size_t)row0 * ldc + col] =
                make_float2(acc[f][p][0], acc[f][p][1]);
            *(float2*)&Cd[(size_t)(row0 + 8) * ldc + col] =
                make_float2(acc[f][p][2], acc[f][p][3]);
        }
    }
}

// ---------------------------------------------------------------------------
// fp32 -> bf16 hi/lo elementwise split
// ---------------------------------------------------------------------------
__global__ void cvt_hilo(const float* __restrict__ x,
                         __nv_bfloat16* __restrict__ hi,
                         __nv_bfloat16* __restrict__ lo, int n)
{
    int i = blockIdx.x * blockDim.x + threadIdx.x;
    if (i >= n) return;
    float v = x[i];
    __nv_bfloat16 h = __float2bfloat16(v);
    hi[i] = h;
    lo[i] = __float2bfloat16(v - __bfloat162float(h));
}

// W[K,N] fp32 -> Wt[N,K] bf16 hi/lo (transpose + split); single-weight form
__global__ void transpose_cvt(const float* __restrict__ W,
                              __nv_bfloat16* __restrict__ Th,
                              __nv_bfloat16* __restrict__ Tl, int K, int N)
{
    __shared__ float tile[32][33];
    int kb = blockIdx.y * 32, nb = blockIdx.x * 32;
    int tx = threadIdx.x, ty = threadIdx.y;
#pragma unroll
    for (int i = ty; i < 32; i += 8)
        tile[i][tx] = W[(size_t)(kb + i) * N + nb + tx];
    __syncthreads();
#pragma unroll
    for (int i = ty; i < 32; i += 8) {
        float v = tile[tx][i];                     // = W[kb+tx][nb+i]
        __nv_bfloat16 h = __float2bfloat16(v);
        size_t oidx = (size_t)(nb + i) * K + kb + tx;
        Th[oidx] = h;
        Tl[oidx] = __float2bfloat16(v - __bfloat162float(h));
    }
}

// Fused transpose of Wq|Wk|Wv|Wg into the [6144][1024] buffer (one launch).
__global__ void transpose_all(const float* __restrict__ Wq,
                              const float* __restrict__ Wk,
                              const float* __restrict__ Wv,
                              const float* __restrict__ Wg,
                              __nv_bfloat16* __restrict__ Th,
                              __nv_bfloat16* __restrict__ Tl)
{
    __shared__ float tile[32][33];
    int bid = blockIdx.x;
    const float* W; int N; size_t off;
    if (bid < 1024)      { W = Wq; N = KEYDIM; off = 0;                  }
    else if (bid < 2048) { W = Wk; N = KEYDIM; off = (size_t)1024*ND; bid -= 1024; }
    else if (bid < 4096) { W = Wv; N = VALDIM; off = (size_t)2048*ND; bid -= 2048; }
    else                 { W = Wg; N = VALDIM; off = (size_t)4096*ND; bid -= 4096; }
    int nblk = N / 32;
    int nb = (bid % nblk) * 32;
    int kb = (bid / nblk) * 32;
    int tx = threadIdx.x, ty = threadIdx.y;
#pragma unroll
    for (int i = ty; i < 32; i += 8)
        tile[i][tx] = W[(size_t)(kb + i) * N + nb + tx];
    __syncthreads();
#pragma unroll
    for (int i = ty; i < 32; i += 8) {
        float v = tile[tx][i];
        __nv_bfloat16 h = __float2bfloat16(v);
        size_t oidx = off + (size_t)(nb + i) * ND + kb + tx;
        Th[oidx] = h;
        Tl[oidx] = __float2bfloat16(v - __bfloat162float(h));
    }
}

// ---------------------------------------------------------------------------
// Wa/Wb fused: pre-transpose to Wt[16][1024], then warp-per-token dot.
// ---------------------------------------------------------------------------
__global__ void build_wtab(const float* __restrict__ Wa,
                           const float* __restrict__ Wb,
                           float* __restrict__ Wt)
{
    int i = blockIdx.x * blockDim.x + threadIdx.x;
    if (i >= 16 * ND) return;
    int o = i / ND, k = i - o * ND;
    Wt[i] = (o < 8) ? Wa[(size_t)k * NH + o] : Wb[(size_t)k * NH + (o - 8)];
}

__global__ __launch_bounds__(256) void abproj_kernel(
    const float* __restrict__ x, const float* __restrict__ Wt,
    float* __restrict__ apre, float* __restrict__ bpre)
{
    int warp = (blockIdx.x * blockDim.x + threadIdx.x) >> 5;   // token
    int lane = threadIdx.x & 31;
    if (warp >= NTOK) return;
    const float* xr = x + (size_t)warp * ND;

    float acc[16];
#pragma unroll
    for (int o = 0; o < 16; o++) acc[o] = 0.f;

    for (int k0 = 0; k0 < ND; k0 += 32) {
        float xv = xr[k0 + lane];
#pragma unroll
        for (int o = 0; o < 16; o++)
            acc[o] += xv * Wt[o * ND + k0 + lane];
    }
#pragma unroll
    for (int o = 0; o < 16; o++) {
#pragma unroll
        for (int off = 16; off > 0; off >>= 1)
            acc[o] += __shfl_xor_sync(0xffffffffu, acc[o], off);
    }
    if (lane == 0) {
#pragma unroll
        for (int o = 0; o < 8; o++) {
            apre[(size_t)warp * 8 + o] = acc[o];
            bpre[(size_t)warp * 8 + o] = acc[8 + o];
        }
    }
}

// ---------------------------------------------------------------------------
// alpha/beta epilogue
// ---------------------------------------------------------------------------
__global__ void ab_kernel(const float* __restrict__ apre,
                          const float* __restrict__ bpre,
                          const float* __restrict__ A_log,
                          const float* __restrict__ dt_bias,
                          float* __restrict__ alpha,
                          float* __restrict__ beta)
{
    int i = blockIdx.x * blockDim.x + threadIdx.x;
    if (i >= NTOK*NH) return;
    int h = i & (NH-1);
    float xv = apre[i] + dt_bias[h];
    float sp = (xv > 20.f) ? xv : log1pf(expf(xv));
    alpha[i] = expf(-expf(A_log[h]) * sp);
    float bv = bpre[i];
    beta[i] = 2.f / (1.f + expf(-bv));
}

// ---------------------------------------------------------------------------
// Causal depthwise conv (KS=4) + SiLU (+ optional per-head l2norm)
// ---------------------------------------------------------------------------
template<int C, bool NORM>
__global__ void conv_silu_kernel(const float* __restrict__ xin,
                                 const float* __restrict__ w,
                                 float* __restrict__ out)
{
    int t  = blockIdx.x;
    int tt = t & (NT-1);
    int c4 = threadIdx.x * 4;

    float wc[4][4];
    *(float4*)wc[0] = *(const float4*)&w[(c4+0)*4];
    *(float4*)wc[1] = *(const float4*)&w[(c4+1)*4];
    *(float4*)wc[2] = *(const float4*)&w[(c4+2)*4];
    *(float4*)wc[3] = *(const float4*)&w[(c4+3)*4];

    float acc[4] = {0.f, 0.f, 0.f, 0.f};
#pragma unroll
    for (int j = 0; j < 4; j++) {
        int ts = tt - 3 + j;
        if (ts >= 0) {
            float xr[4];
            *(float4*)xr = *(const float4*)&xin[(size_t)(t-3+j)*C + c4];
#pragma unroll
            for (int ci = 0; ci < 4; ci++)
                acc[ci] += wc[ci][j] * xr[ci];
        }
    }
    float y[4];
#pragma unroll
    for (int ci = 0; ci < 4; ci++) {
        float z = acc[ci];
        y[ci] = z / (1.f + expf(-z));
    }
    if (NORM) {
        float ss = y[0]*y[0] + y[1]*y[1] + y[2]*y[2] + y[3]*y[3];
#pragma unroll
        for (int off = 16; off > 0; off >>= 1)
            ss += __shfl_xor_sync(0xffffffffu, ss, off);
        float n  = sqrtf(ss);
        float sc = 1.f / fmaxf(n, 1e-6f);
#pragma unroll
        for (int ci = 0; ci < 4; ci++) y[ci] *= sc;
    }
    *(float4*)&out[(size_t)t*C + c4] = make_float4(y[0], y[1], y[2], y[3]);
}

// ---------------------------------------------------------------------------
// Gated delta-rule scan — 256 threads/CTA (32 rows x 8 lanes, 16 cols/lane).
// 2 warps per SMSP: the second warp fills shfl/LDS/dependency bubbles that a
// single warp exposed. Output partials (8/row) deferred to the flush phase.
// smem: sk 16K | sq 16K | sv 4K | so8 32K | sa 128 | sb 128 = 68.5KB
// ---------------------------------------------------------------------------
#define SCAN_SMEM (16384 + 16384 + 4096 + 32768 + 128 + 128)

__global__ __launch_bounds__(256, 1) void scan_kernel()
{
    extern __shared__ __align__(16) char ssm[];
    float (*sk)[128]   = (float(*)[128])(ssm);
    float (*sq)[128]   = (float(*)[128])(ssm + 16384);
    float (*sv)[32]    = (float(*)[32]) (ssm + 32768);
    float (*so8)[32][8]= (float(*)[32][8])(ssm + 36864);
    float *sa          = (float*)(ssm + 69632);
    float *sb2         = (float*)(ssm + 69760);

    const int blk = blockIdx.x;
    const int vb  = blk & 7;
    const int h   = (blk >> 3) & 7;
    const int b   = blk >> 6;
    const int vr0 = vb * 32;

    const int tid = threadIdx.x;
    const int row = tid >> 3;              // 0..31
    const int cg  = tid & 7;               // 0..7 (16 cols each)

    float s[16];
#pragma unroll
    for (int j = 0; j < 16; j++) s[j] = 0.f;

    const size_t tok0 = (size_t)b * NT;

    for (int c0 = 0; c0 < NT; c0 += 32) {
        // stage k,q: 32 steps x 32 float4 = 1024 units, 256 threads, 4 iters
#pragma unroll
        for (int l = 0; l < 4; l++) {
            int id = tid + l*256;
            int st = id >> 5;
            int cq = (id & 31) * 4;
            size_t gidx = (tok0 + c0 + st) * (size_t)KEYDIM + h*KDIM + cq;
            *(float4*)&sk[st][cq] = *(const float4*)&g_k[gidx];
            *(float4*)&sq[st][cq] = *(const float4*)&g_q[gidx];
        }
        // stage v: 32 steps x 8 float4 = 256 units, 1 iter
        {
            int st = tid >> 3;
            int vq = (tid & 7) * 4;
            *(float4*)&sv[st][vq] =
                *(const float4*)&g_v[(tok0 + c0 + st) * (size_t)VALDIM + h*VDIM + vr0 + vq];
        }
        if (tid < 32)
            sa[tid] = g_alpha[(tok0 + c0 + tid) * NH + h];
        else if (tid < 64)
            sb2[tid-32] = g_beta[(tok0 + c0 + (tid-32)) * NH + h];
        __syncthreads();

        for (int i = 0; i < 32; i++) {
            float a   = sa[i];
            float bb  = sb2[i];
            float abb = a * bb;
            float vv  = sv[i][row];
            float kf[16];
            const float* kr = &sk[i][cg*16];
            const float* qr = &sq[i][cg*16];
#pragma unroll
            for (int j = 0; j < 4; j++)
                *(float4*)&kf[j*4] = *(const float4*)&kr[j*4];
            // retained = S k  (4 parallel chains of 4, then 3 shfls over 8 lanes)
            float r0 = 0.f, r1 = 0.f, r2 = 0.f, r3 = 0.f;
#pragma unroll
            for (int j = 0; j < 4; j++) {
                r0 += s[j*4+0] * kf[j*4+0];
                r1 += s[j*4+1] * kf[j*4+1];
                r2 += s[j*4+2] * kf[j*4+2];
                r3 += s[j*4+3] * kf[j*4+3];
            }
            float r = (r0 + r1) + (r2 + r3);
            r += __shfl_xor_sync(0xffffffffu, r, 1);
            // overlap shfl latency with q loads
            float qf[16];
#pragma unroll
            for (int j = 0; j < 4; j++)
                *(float4*)&qf[j*4] = *(const float4*)&qr[j*4];
            r += __shfl_xor_sync(0xffffffffu, r, 2);
            r += __shfl_xor_sync(0xffffffffu, r, 4);
            float c = bb*vv - abb*r;
            // state update + per-lane partial output (no shfl on critical path)
            float o0 = 0.f, o1 = 0.f, o2 = 0.f, o3 = 0.f;
#pragma unroll
            for (int j = 0; j < 4; j++) {
                s[j*4+0] = a*s[j*4+0] + c*kf[j*4+0]; o0 += s[j*4+0]*qf[j*4+0];
                s[j*4+1] = a*s[j*4+1] + c*kf[j*4+1]; o1 += s[j*4+1]*qf[j*4+1];
                s[j*4+2] = a*s[j*4+2] + c*kf[j*4+2]; o2 += s[j*4+2]*qf[j*4+2];
                s[j*4+3] = a*s[j*4+3] + c*kf[j*4+3]; o3 += s[j*4+3]*qf[j*4+3];
            }
            so8[i][row][cg] = (o0 + o1) + (o2 + o3);
        }
        __syncthreads();

        // flush: 8-way partial sum + coalesced store (1024 outputs, 4 iters)
#pragma unroll
        for (int l = 0; l < 4; l++) {
            int id = tid + l*256;
            int st = id >> 5;
            int rr = id & 31;
            float4 p0 = *(float4*)&so8[st][rr][0];
            float4 p1 = *(float4*)&so8[st][rr][4];
            g_o[(tok0 + c0 + st) * (size_t)VALDIM + h*VDIM + vr0 + rr] =
                ((p0.x + p0.y) + (p0.z + p0.w)) + ((p1.x + p1.y) + (p1.z + p1.w));
        }
    }
}

// ---------------------------------------------------------------------------
// Gating epilogue: writes bf16 hi/lo directly (feeds Wo GEMM)
// ---------------------------------------------------------------------------
__global__ void gate_kernel(const float* __restrict__ o,
                            const float* __restrict__ gate,
                            const float* __restrict__ w,
                            __nv_bfloat16* __restrict__ oh,
                            __nv_bfloat16* __restrict__ ol)
{
    int bh = blockIdx.x;
    size_t base = (size_t)bh * VDIM;
    int tid = threadIdx.x;

    float v  = o[base + tid];
    float ss = v*v;
#pragma unroll
    for (int off = 16; off > 0; off >>= 1)
        ss += __shfl_xor_sync(0xffffffffu, ss, off);
    __shared__ float red[8];
    if ((tid & 31) == 0) red[tid >> 5] = ss;
    __syncthreads();
    float tot = red[0]+red[1]+red[2]+red[3]+red[4]+red[5]+red[6]+red[7];
    float rms = rsqrtf(tot * (1.f/VDIM) + 1e-5f);

    float gv = gate[base + tid];
    float sg = gv / (1.f + expf(-gv));
    float val = v * rms * w[tid] * sg;
    __nv_bfloat16 hi = __float2bfloat16(val);
    oh[base + tid] = hi;
    ol[base + tid] = __float2bfloat16(val - __bfloat162float(hi));
}

// ---------------------------------------------------------------------------
// launch
// ---------------------------------------------------------------------------
extern "C" void kernel_launch(void* const* d_in, const int* in_sizes, int n_in,
                              void* d_out, int out_size)
{
    const float* x       = (const float*)d_in[0];
    const float* Wq      = (const float*)d_in[1];
    const float* Wk      = (const float*)d_in[2];
    const float* Wv      = (const float*)d_in[3];
    const float* Wa      = (const float*)d_in[4];
    const float* Wb      = (const float*)d_in[5];
    const float* Wg      = (const float*)d_in[6];
    const float* Wo      = (const float*)d_in[7];
    const float* A_log   = (const float*)d_in[8];
    const float* dt_bias = (const float*)d_in[9];
    const float* conv_q  = (const float*)d_in[10];
    const float* conv_k  = (const float*)d_in[11];
    const float* conv_v  = (const float*)d_in[12];
    const float* o_nw    = (const float*)d_in[13];
    float* out = (float*)d_out;

    float *qpre, *kpre, *vpre, *gatep, *obuf;
    float *apre, *bpre, *alpha, *beta, *wtab;
    __nv_bfloat16 *xh, *xl, *oh, *ol, *wth, *wtl;
    cudaGetSymbolAddress((void**)&qpre,  g_qpre);
    cudaGetSymbolAddress((void**)&kpre,  g_kpre);
    cudaGetSymbolAddress((void**)&vpre,  g_vpre);
    cudaGetSymbolAddress((void**)&gatep, g_gate);
    cudaGetSymbolAddress((void**)&obuf,  g_o);
    cudaGetSymbolAddress((void**)&apre,  g_apre);
    cudaGetSymbolAddress((void**)&bpre,  g_bpre);
    cudaGetSymbolAddress((void**)&alpha, g_alpha);
    cudaGetSymbolAddress((void**)&beta,  g_beta);
    cudaGetSymbolAddress((void**)&wtab,  g_wtab);
    cudaGetSymbolAddress((void**)&xh,    g_xh);
    cudaGetSymbolAddress((void**)&xl,    g_xl);
    cudaGetSymbolAddress((void**)&oh,    g_oh);
    cudaGetSymbolAddress((void**)&ol,    g_ol);
    cudaGetSymbolAddress((void**)&wth,   g_wth);
    cudaGetSymbolAddress((void**)&wtl,   g_wtl);
    float *q, *k, *v;
    cudaGetSymbolAddress((void**)&q, g_q);
    cudaGetSymbolAddress((void**)&k, g_k);
    cudaGetSymbolAddress((void**)&v, g_v);

    cudaFuncSetAttribute(gemm_mma<0>, cudaFuncAttributeMaxDynamicSharedMemorySize,
                         GEMM_SMEM);
    cudaFuncSetAttribute(gemm_mma<1>, cudaFuncAttributeMaxDynamicSharedMemorySize,
                         GEMM_SMEM);
    cudaFuncSetAttribute(scan_kernel, cudaFuncAttributeMaxDynamicSharedMemorySize,
                         SCAN_SMEM);

    dim3 tb(32, 8);

    // 1) split x into bf16 hi/lo
    cvt_hilo<<<(NTOK*ND + 255)/256, 256>>>(x, xh, xl, NTOK*ND);
    // 2) all 4 projection weight transposes in one launch
    transpose_all<<<6144, tb>>>(Wq, Wk, Wv, Wg, wth, wtl);
    // 3) Wa|Wb transpose table
    build_wtab<<<(16*ND + 255)/256, 256>>>(Wa, Wb, wtab);
    // 4) fused projection GEMM  <-- ncu capture slot
    gemm_mma<1><<<dim3(NPROJ/128, NTOK/128), 256, GEMM_SMEM>>>(
        xh, xl, wth, wtl, qpre, kpre, vpre, gatep, 0, ND);

    // Wa/Wb small-N projection
    abproj_kernel<<<(NTOK*32 + 255)/256, 256>>>(x, wtab, apre, bpre);
    ab_kernel<<<(NTOK*NH + 255)/256, 256>>>(apre, bpre, A_log, dt_bias, alpha, beta);

    conv_silu_kernel<KEYDIM, true ><<<NTOK, KEYDIM/4>>>(qpre, conv_q, q);
    conv_silu_kernel<KEYDIM, true ><<<NTOK, KEYDIM/4>>>(kpre, conv_k, k);
    conv_silu_kernel<VALDIM, false><<<NTOK, VALDIM/4>>>(vpre, conv_v, v);

    scan_kernel<<<NB*NH*8, 256, SCAN_SMEM>>>();

    gate_kernel<<<NTOK*NH, VDIM>>>(obuf, gatep, o_nw, oh, ol);

    // Output projection
    transpose_cvt<<<dim3(ND/32, VALDIM/32), tb>>>(Wo, wth, wtl, VALDIM, ND);
    gemm_mma<0><<<dim3(ND/128, NTOK/128), 256, GEMM_SMEM>>>(
        oh, ol, wth, wtl, out, nullptr, nullptr, nullptr, ND, VALDIM);
}

// round 12
// speedup vs baseline: 1.0330x; 1.0024x over previous
#include <cuda_runtime.h>
#include <cuda_bf16.h>
#include <math.h>
#include <stddef.h>
#include <stdint.h>

// Problem constants
#define NB 2
#define NT 2048
#define ND 1024
#define NH 8
#define KDIM 128
#define VDIM 256
#define NTOK (NB*NT)       // 4096
#define KEYDIM 1024
#define VALDIM 2048
#define NPROJ 6144         // q(1024) | k(1024) | v(2048) | g(2048)

// ---------------------------------------------------------------------------
// Scratch (static device globals; no allocation in kernel_launch)
// ---------------------------------------------------------------------------
__device__ float g_qpre[(size_t)NTOK*KEYDIM];
__device__ float g_kpre[(size_t)NTOK*KEYDIM];
__device__ float g_vpre[(size_t)NTOK*VALDIM];
__device__ float g_q   [(size_t)NTOK*KEYDIM];
__device__ float g_k   [(size_t)NTOK*KEYDIM];
__device__ float g_v   [(size_t)NTOK*VALDIM];
__device__ float g_gate[(size_t)NTOK*VALDIM];
__device__ float g_o   [(size_t)NTOK*VALDIM];
__device__ float g_apre[(size_t)NTOK*NH];
__device__ float g_bpre[(size_t)NTOK*NH];
__device__ float g_alpha[(size_t)NTOK*NH];
__device__ float g_beta [(size_t)NTOK*NH];
__device__ float g_wtab [(size_t)16*ND];

// bf16 hi/lo split scratch for tensor-core GEMMs
__device__ __align__(16) __nv_bfloat16 g_xh[(size_t)NTOK*ND];
__device__ __align__(16) __nv_bfloat16 g_xl[(size_t)NTOK*ND];
__device__ __align__(16) __nv_bfloat16 g_oh[(size_t)NTOK*VALDIM];
__device__ __align__(16) __nv_bfloat16 g_ol[(size_t)NTOK*VALDIM];
// transposed weights [N,K] bf16 hi/lo; sized for fused proj (6144x1024)
__device__ __align__(16) __nv_bfloat16 g_wth[(size_t)NPROJ*ND];
__device__ __align__(16) __nv_bfloat16 g_wtl[(size_t)NPROJ*ND];

// ---------------------------------------------------------------------------
// helpers
// ---------------------------------------------------------------------------
__device__ __forceinline__ uint32_t smem_u32(const void* p) {
    uint32_t a;
    asm("{ .reg .u64 t; cvta.to.shared.u64 t, %1; cvt.u32.u64 %0, t; }"
        : "=r"(a) : "l"(p));
    return a;
}

#define CP_ASYNC16(dst, src) \
    asm volatile("cp.async.cg.shared.global [%0], [%1], 16;" :: "r"(dst), "l"(src))
#define CP_COMMIT() asm volatile("cp.async.commit_group;")
#define CP_WAIT(n)  asm volatile("cp.async.wait_group %0;" :: "n"(n))

#define LDMX4(r, addr) \
    asm volatile("ldmatrix.sync.aligned.m8n8.x4.shared.b16 {%0,%1,%2,%3}, [%4];" \
        : "=r"((r)[0]), "=r"((r)[1]), "=r"((r)[2]), "=r"((r)[3]) : "r"(addr))

#define MMA_BF16(c, a, b) \
    asm volatile("mma.sync.aligned.m16n8k16.row.col.f32.bf16.bf16.f32 " \
        "{%0,%1,%2,%3}, {%4,%5,%6,%7}, {%8,%9}, {%0,%1,%2,%3};" \
        : "+f"((c)[0]), "+f"((c)[1]), "+f"((c)[2]), "+f"((c)[3]) \
        : "r"((a)[0]), "r"((a)[1]), "r"((a)[2]), "r"((a)[3]), \
          "r"((b)[0]), "r"((b)[1]))

// fast sigmoid/silu (MUFU.EX2 based; rel err ~2^-21, tolerance is 1e-3)
__device__ __forceinline__ float fast_sigmoid(float z) {
    return __fdividef(1.f, 1.f + __expf(-z));
}
__device__ __forceinline__ float fast_silu(float z) {
    return z * fast_sigmoid(z);
}

// ---------------------------------------------------------------------------
// Tensor-core GEMM (legacy mma.sync, base sm_100 ISA) — R6 best config:
// CTA tile 128x128, BK=32, 256 threads (8 warps = 4m x 2n, warp tile 32x64),
// cp.async 3-stage pipeline, 80B smem row stride (ldmatrix conflict-free).
// ---------------------------------------------------------------------------
#define TILE_B   10240            // 128 rows * 80 bytes
#define STAGE_B  (4*TILE_B)       // Ah, Al, Bh, Bl
#define GEMM_SMEM (3*STAGE_B)     // 122880 (3-stage)

__device__ __forceinline__ void g2s_chunk(
    uint32_t dbase, const __nv_bfloat16* Ah, const __nv_bfloat16* Al,
    const __nv_bfloat16* Bh, const __nv_bfloat16* Bl,
    int m0, int n0, int k0, int K, int tid)
{
    const __nv_bfloat16* srcs[4] = {
        Ah + (size_t)m0 * K + k0, Al + (size_t)m0 * K + k0,
        Bh + (size_t)n0 * K + k0, Bl + (size_t)n0 * K + k0 };
#pragma unroll
    for (int t = 0; t < 4; t++) {
        const __nv_bfloat16* src = srcs[t];
        uint32_t db = dbase + t * TILE_B;
#pragma unroll
        for (int l = 0; l < 2; l++) {
            int id  = tid + l * 256;       // 0..511
            int row = id >> 2;             // 0..127
            int q   = id & 3;              // 16B unit (8 bf16)
            CP_ASYNC16(db + row * 80 + q * 16, src + (size_t)row * K + q * 8);
        }
    }
}

template<int FUSED>
__global__ __launch_bounds__(256, 1) void gemm_mma(
    const __nv_bfloat16* __restrict__ Ah, const __nv_bfloat16* __restrict__ Al,
    const __nv_bfloat16* __restrict__ Bh, const __nv_bfloat16* __restrict__ Bl,
    float* __restrict__ C0, float* __restrict__ C1,
    float* __restrict__ C2, float* __restrict__ C3,
    int Nsingle, int K)
{
    extern __shared__ __align__(16) char smem[];
    const uint32_t sbase = smem_u32(smem);
    const int tid  = threadIdx.x;
    const int wid  = tid >> 5, lane = tid & 31;
    const int wm   = wid >> 1, wn = wid & 1;
    const int m0   = blockIdx.y * 128;
    const int n0   = blockIdx.x * 128;

    const int mat = lane >> 3;             // ldmatrix quadrant
    const int r   = lane & 7;

    float acc[2][8][4];
#pragma unroll
    for (int f = 0; f < 2; f++)
#pragma unroll
        for (int p = 0; p < 8; p++)
#pragma unroll
            for (int j = 0; j < 4; j++) acc[f][p][j] = 0.f;

    const int nc = K >> 5;

    // prologue: chunks 0,1 -> stages 0,1
    g2s_chunk(sbase, Ah, Al, Bh, Bl, m0, n0, 0, K, tid);
    CP_COMMIT();
    if (nc > 1) {
        g2s_chunk(sbase + STAGE_B, Ah, Al, Bh, Bl, m0, n0, 32, K, tid);
        CP_COMMIT();
    }

    for (int c = 0; c < nc; c++) {
        if (c + 2 < nc) {
            g2s_chunk(sbase + ((c + 2) % 3) * STAGE_B,
                      Ah, Al, Bh, Bl, m0, n0, (c + 2) << 5, K, tid);
            CP_COMMIT();
            CP_WAIT(2);
        } else if (c + 1 < nc) {
            CP_WAIT(1);
        } else {
            CP_WAIT(0);
        }
        __syncthreads();

        const uint32_t ab  = sbase + (c % 3) * STAGE_B;          // Ah tile
        const uint32_t alb = ab + TILE_B;
        const uint32_t bhb = ab + 2 * TILE_B;
        const uint32_t blb = ab + 3 * TILE_B;

#pragma unroll
        for (int ks = 0; ks < 2; ks++) {
            uint32_t fa_h[2][4], fa_l[2][4];
#pragma unroll
            for (int f = 0; f < 2; f++) {
                int row  = wm * 32 + f * 16 + ((mat & 1) << 3) + r;
                int kcol = ks * 16 + ((mat >> 1) << 3);
                uint32_t off = row * 80 + kcol * 2;
                LDMX4(fa_h[f], ab  + off);
                LDMX4(fa_l[f], alb + off);
            }
            uint32_t fb_h[8][2], fb_l[8][2];
#pragma unroll
            for (int p = 0; p < 4; p++) {
                int row  = wn * 64 + p * 16 + ((mat >> 1) << 3) + r;
                int kcol = ks * 16 + ((mat & 1) << 3);
                uint32_t off = row * 80 + kcol * 2;
                uint32_t t4[4];
                LDMX4(t4, bhb + off);
                fb_h[p*2][0] = t4[0]; fb_h[p*2][1] = t4[1];
                fb_h[p*2+1][0] = t4[2]; fb_h[p*2+1][1] = t4[3];
                LDMX4(t4, blb + off);
                fb_l[p*2][0] = t4[0]; fb_l[p*2][1] = t4[1];
                fb_l[p*2+1][0] = t4[2]; fb_l[p*2+1][1] = t4[3];
            }
#pragma unroll
            for (int f = 0; f < 2; f++)
#pragma unroll
                for (int p = 0; p < 8; p++) {
                    MMA_BF16(acc[f][p], fa_h[f], fb_h[p]);
                    MMA_BF16(acc[f][p], fa_h[f], fb_l[p]);
                    MMA_BF16(acc[f][p], fa_l[f], fb_h[p]);
                }
        }
        __syncthreads();
    }

    // epilogue: pick destination buffer / ld / column base
    float* Cd; int ldc, cb;
    if (FUSED) {
        if (n0 < 1024)      { Cd = C0; ldc = 1024; cb = n0; }
        else if (n0 < 2048) { Cd = C1; ldc = 1024; cb = n0 - 1024; }
        else if (n0 < 4096) { Cd = C2; ldc = 2048; cb = n0 - 2048; }
        else                { Cd = C3; ldc = 2048; cb = n0 - 4096; }
    } else {
        Cd = C0; ldc = Nsingle; cb = n0;
    }
#pragma unroll
    for (int f = 0; f < 2; f++) {
        int row0 = m0 + wm * 32 + f * 16 + (lane >> 2);
#pragma unroll
        for (int p = 0; p < 8; p++) {
            int col = cb + wn * 64 + p * 8 + (lane & 3) * 2;
            *(float2*)&Cd[(size_t)row0 * ldc + col] =
                make_float2(acc[f][p][0], acc[f][p][1]);
            *(float2*)&Cd[(size_t)(row0 + 8) * ldc + col] =
                make_float2(acc[f][p][2], acc[f][p][3]);
        }
    }
}

// ---------------------------------------------------------------------------
// fp32 -> bf16 hi/lo elementwise split
// ---------------------------------------------------------------------------
__global__ void cvt_hilo(const float* __restrict__ x,
                         __nv_bfloat16* __restrict__ hi,
                         __nv_bfloat16* __restrict__ lo, int n)
{
    int i = blockIdx.x * blockDim.x + threadIdx.x;
    if (i >= n) return;
    float v = x[i];
    __nv_bfloat16 h = __float2bfloat16(v);
    hi[i] = h;
    lo[i] = __float2bfloat16(v - __bfloat162float(h));
}

// W[K,N] fp32 -> Wt[N,K] bf16 hi/lo (transpose + split); single-weight form
__global__ void transpose_cvt(const float* __restrict__ W,
                              __nv_bfloat16* __restrict__ Th,
                              __nv_bfloat16* __restrict__ Tl, int K, int N)
{
    __shared__ float tile[32][33];
    int kb = blockIdx.y * 32, nb = blockIdx.x * 32;
    int tx = threadIdx.x, ty = threadIdx.y;
#pragma unroll
    for (int i = ty; i < 32; i += 8)
        tile[i][tx] = W[(size_t)(kb + i) * N + nb + tx];
    __syncthreads();
#pragma unroll
    for (int i = ty; i < 32; i += 8) {
        float v = tile[tx][i];                     // = W[kb+tx][nb+i]
        __nv_bfloat16 h = __float2bfloat16(v);
        size_t oidx = (size_t)(nb + i) * K + kb + tx;
        Th[oidx] = h;
        Tl[oidx] = __float2bfloat16(v - __bfloat162float(h));
    }
}

// Fused transpose of Wq|Wk|Wv|Wg into the [6144][1024] buffer (one launch).
__global__ void transpose_all(const float* __restrict__ Wq,
                              const float* __restrict__ Wk,
                              const float* __restrict__ Wv,
                              const float* __restrict__ Wg,
                              __nv_bfloat16* __restrict__ Th,
                              __nv_bfloat16* __restrict__ Tl)
{
    __shared__ float tile[32][33];
    int bid = blockIdx.x;
    const float* W; int N; size_t off;
    if (bid < 1024)      { W = Wq; N = KEYDIM; off = 0;                  }
    else if (bid < 2048) { W = Wk; N = KEYDIM; off = (size_t)1024*ND; bid -= 1024; }
    else if (bid < 4096) { W = Wv; N = VALDIM; off = (size_t)2048*ND; bid -= 2048; }
    else                 { W = Wg; N = VALDIM; off = (size_t)4096*ND; bid -= 4096; }
    int nblk = N / 32;
    int nb = (bid % nblk) * 32;
    int kb = (bid / nblk) * 32;
    int tx = threadIdx.x, ty = threadIdx.y;
#pragma unroll
    for (int i = ty; i < 32; i += 8)
        tile[i][tx] = W[(size_t)(kb + i) * N + nb + tx];
    __syncthreads();
#pragma unroll
    for (int i = ty; i < 32; i += 8) {
        float v = tile[tx][i];
        __nv_bfloat16 h = __float2bfloat16(v);
        size_t oidx = off + (size_t)(nb + i) * ND + kb + tx;
        Th[oidx] = h;
        Tl[oidx] = __float2bfloat16(v - __bfloat162float(h));
    }
}

// ---------------------------------------------------------------------------
// Wa/Wb fused: pre-transpose to Wt[16][1024], then warp-per-token dot.
// ---------------------------------------------------------------------------
__global__ void build_wtab(const float* __restrict__ Wa,
                           const float* __restrict__ Wb,
                           float* __restrict__ Wt)
{
    int i = blockIdx.x * blockDim.x + threadIdx.x;
    if (i >= 16 * ND) return;
    int o = i / ND, k = i - o * ND;
    Wt[i] = (o < 8) ? Wa[(size_t)k * NH + o] : Wb[(size_t)k * NH + (o - 8)];
}

__global__ __launch_bounds__(256) void abproj_kernel(
    const float* __restrict__ x, const float* __restrict__ Wt,
    float* __restrict__ apre, float* __restrict__ bpre)
{
    int warp = (blockIdx.x * blockDim.x + threadIdx.x) >> 5;   // token
    int lane = threadIdx.x & 31;
    if (warp >= NTOK) return;
    const float* xr = x + (size_t)warp * ND;

    float acc[16];
#pragma unroll
    for (int o = 0; o < 16; o++) acc[o] = 0.f;

    for (int k0 = 0; k0 < ND; k0 += 32) {
        float xv = xr[k0 + lane];
#pragma unroll
        for (int o = 0; o < 16; o++)
            acc[o] += xv * Wt[o * ND + k0 + lane];
    }
#pragma unroll
    for (int o = 0; o < 16; o++) {
#pragma unroll
        for (int off = 16; off > 0; off >>= 1)
            acc[o] += __shfl_xor_sync(0xffffffffu, acc[o], off);
    }
    if (lane == 0) {
#pragma unroll
        for (int o = 0; o < 8; o++) {
            apre[(size_t)warp * 8 + o] = acc[o];
            bpre[(size_t)warp * 8 + o] = acc[8 + o];
        }
    }
}

// ---------------------------------------------------------------------------
// alpha/beta epilogue  (accurate softplus guard; fast exp/sigmoid elsewhere)
// ---------------------------------------------------------------------------
__global__ void ab_kernel(const float* __restrict__ apre,
                          const float* __restrict__ bpre,
                          const float* __restrict__ A_log,
                          const float* __restrict__ dt_bias,
                          float* __restrict__ alpha,
                          float* __restrict__ beta)
{
    int i = blockIdx.x * blockDim.x + threadIdx.x;
    if (i >= NTOK*NH) return;
    int h = i & (NH-1);
    float xv = apre[i] + dt_bias[h];
    float sp = (xv > 20.f) ? xv : log1pf(expf(xv));   // small kernel: keep accurate
    alpha[i] = expf(-expf(A_log[h]) * sp);
    beta[i] = 2.f * fast_sigmoid(bpre[i]);
}

// ---------------------------------------------------------------------------
// Causal depthwise conv (KS=4) + SiLU (+ optional per-head l2norm)
// Fast-math SiLU: the accurate expf (~20 instrs) was the hidden elementwise
// cost (~16M expf across the 3 conv launches).
// ---------------------------------------------------------------------------
template<int C, bool NORM>
__global__ void conv_silu_kernel(const float* __restrict__ xin,
                                 const float* __restrict__ w,
                                 float* __restrict__ out)
{
    int t  = blockIdx.x;
    int tt = t & (NT-1);
    int c4 = threadIdx.x * 4;

    float wc[4][4];
    *(float4*)wc[0] = *(const float4*)&w[(c4+0)*4];
    *(float4*)wc[1] = *(const float4*)&w[(c4+1)*4];
    *(float4*)wc[2] = *(const float4*)&w[(c4+2)*4];
    *(float4*)wc[3] = *(const float4*)&w[(c4+3)*4];

    float acc[4] = {0.f, 0.f, 0.f, 0.f};
#pragma unroll
    for (int j = 0; j < 4; j++) {
        int ts = tt - 3 + j;
        if (ts >= 0) {
            float xr[4];
            *(float4*)xr = *(const float4*)&xin[(size_t)(t-3+j)*C + c4];
#pragma unroll
            for (int ci = 0; ci < 4; ci++)
                acc[ci] += wc[ci][j] * xr[ci];
        }
    }
    float y[4];
#pragma unroll
    for (int ci = 0; ci < 4; ci++)
        y[ci] = fast_silu(acc[ci]);
    if (NORM) {
        float ss = y[0]*y[0] + y[1]*y[1] + y[2]*y[2] + y[3]*y[3];
#pragma unroll
        for (int off = 16; off > 0; off >>= 1)
            ss += __shfl_xor_sync(0xffffffffu, ss, off);
        float n  = sqrtf(ss);
        float sc = __fdividef(1.f, fmaxf(n, 1e-6f));
#pragma unroll
        for (int ci = 0; ci < 4; ci++) y[ci] *= sc;
    }
    *(float4*)&out[(size_t)t*C + c4] = make_float4(y[0], y[1], y[2], y[3]);
}

// ---------------------------------------------------------------------------
// Gated delta-rule scan — 256 threads/CTA (32 rows x 8 lanes, 16 cols/lane).
// ---------------------------------------------------------------------------
#define SCAN_SMEM (16384 + 16384 + 4096 + 32768 + 128 + 128)

__global__ __launch_bounds__(256, 1) void scan_kernel()
{
    extern __shared__ __align__(16) char ssm[];
    float (*sk)[128]   = (float(*)[128])(ssm);
    float (*sq)[128]   = (float(*)[128])(ssm + 16384);
    float (*sv)[32]    = (float(*)[32]) (ssm + 32768);
    float (*so8)[32][8]= (float(*)[32][8])(ssm + 36864);
    float *sa          = (float*)(ssm + 69632);
    float *sb2         = (float*)(ssm + 69760);

    const int blk = blockIdx.x;
    const int vb  = blk & 7;
    const int h   = (blk >> 3) & 7;
    const int b   = blk >> 6;
    const int vr0 = vb * 32;

    const int tid = threadIdx.x;
    const int row = tid >> 3;              // 0..31
    const int cg  = tid & 7;               // 0..7 (16 cols each)

    float s[16];
#pragma unroll
    for (int j = 0; j < 16; j++) s[j] = 0.f;

    const size_t tok0 = (size_t)b * NT;

    for (int c0 = 0; c0 < NT; c0 += 32) {
#pragma unroll
        for (int l = 0; l < 4; l++) {
            int id = tid + l*256;
            int st = id >> 5;
            int cq = (id & 31) * 4;
            size_t gidx = (tok0 + c0 + st) * (size_t)KEYDIM + h*KDIM + cq;
            *(float4*)&sk[st][cq] = *(const float4*)&g_k[gidx];
            *(float4*)&sq[st][cq] = *(const float4*)&g_q[gidx];
        }
        {
            int st = tid >> 3;
            int vq = (tid & 7) * 4;
            *(float4*)&sv[st][vq] =
                *(const float4*)&g_v[(tok0 + c0 + st) * (size_t)VALDIM + h*VDIM + vr0 + vq];
        }
        if (tid < 32)
            sa[tid] = g_alpha[(tok0 + c0 + tid) * NH + h];
        else if (tid < 64)
            sb2[tid-32] = g_beta[(tok0 + c0 + (tid-32)) * NH + h];
        __syncthreads();

        for (int i = 0; i < 32; i++) {
            float a   = sa[i];
            float bb  = sb2[i];
            float abb = a * bb;
            float vv  = sv[i][row];
            float kf[16];
            const float* kr = &sk[i][cg*16];
            const float* qr = &sq[i][cg*16];
#pragma unroll
            for (int j = 0; j < 4; j++)
                *(float4*)&kf[j*4] = *(const float4*)&kr[j*4];
            float r0 = 0.f, r1 = 0.f, r2 = 0.f, r3 = 0.f;
#pragma unroll
            for (int j = 0; j < 4; j++) {
                r0 += s[j*4+0] * kf[j*4+0];
                r1 += s[j*4+1] * kf[j*4+1];
                r2 += s[j*4+2] * kf[j*4+2];
                r3 += s[j*4+3] * kf[j*4+3];
            }
            float r = (r0 + r1) + (r2 + r3);
            r += __shfl_xor_sync(0xffffffffu, r, 1);
            float qf[16];
#pragma unroll
            for (int j = 0; j < 4; j++)
                *(float4*)&qf[j*4] = *(const float4*)&qr[j*4];
            r += __shfl_xor_sync(0xffffffffu, r, 2);
            r += __shfl_xor_sync(0xffffffffu, r, 4);
            float c = bb*vv - abb*r;
            float o0 = 0.f, o1 = 0.f, o2 = 0.f, o3 = 0.f;
#pragma unroll
            for (int j = 0; j < 4; j++) {
                s[j*4+0] = a*s[j*4+0] + c*kf[j*4+0]; o0 += s[j*4+0]*qf[j*4+0];
                s[j*4+1] = a*s[j*4+1] + c*kf[j*4+1]; o1 += s[j*4+1]*qf[j*4+1];
                s[j*4+2] = a*s[j*4+2] + c*kf[j*4+2]; o2 += s[j*4+2]*qf[j*4+2];
                s[j*4+3] = a*s[j*4+3] + c*kf[j*4+3]; o3 += s[j*4+3]*qf[j*4+3];
            }
            so8[i][row][cg] = (o0 + o1) + (o2 + o3);
        }
        __syncthreads();

#pragma unroll
        for (int l = 0; l < 4; l++) {
            int id = tid + l*256;
            int st = id >> 5;
            int rr = id & 31;
            float4 p0 = *(float4*)&so8[st][rr][0];
            float4 p1 = *(float4*)&so8[st][rr][4];
            g_o[(tok0 + c0 + st) * (size_t)VALDIM + h*VDIM + vr0 + rr] =
                ((p0.x + p0.y) + (p0.z + p0.w)) + ((p1.x + p1.y) + (p1.z + p1.w));
        }
    }
}

// ---------------------------------------------------------------------------
// Gating epilogue: fast-math sigmoid (8.4M accurate expf was ~300us); writes
// bf16 hi/lo directly (feeds Wo GEMM)
// ---------------------------------------------------------------------------
__global__ void gate_kernel(const float* __restrict__ o,
                            const float* __restrict__ gate,
                            const float* __restrict__ w,
                            __nv_bfloat16* __restrict__ oh,
                            __nv_bfloat16* __restrict__ ol)
{
    int bh = blockIdx.x;
    size_t base = (size_t)bh * VDIM;
    int tid = threadIdx.x;

    float v  = o[base + tid];
    float ss = v*v;
#pragma unroll
    for (int off = 16; off > 0; off >>= 1)
        ss += __shfl_xor_sync(0xffffffffu, ss, off);
    __shared__ float red[8];
    if ((tid & 31) == 0) red[tid >> 5] = ss;
    __syncthreads();
    float tot = red[0]+red[1]+red[2]+red[3]+red[4]+red[5]+red[6]+red[7];
    float rms = rsqrtf(tot * (1.f/VDIM) + 1e-5f);

    float sg = fast_silu(gate[base + tid]);
    float val = v * rms * w[tid] * sg;
    __nv_bfloat16 hi = __float2bfloat16(val);
    oh[base + tid] = hi;
    ol[base + tid] = __float2bfloat16(val - __bfloat162float(hi));
}

// ---------------------------------------------------------------------------
// launch
// ---------------------------------------------------------------------------
extern "C" void kernel_launch(void* const* d_in, const int* in_sizes, int n_in,
                              void* d_out, int out_size)
{
    const float* x       = (const float*)d_in[0];
    const float* Wq      = (const float*)d_in[1];
    const float* Wk      = (const float*)d_in[2];
    const float* Wv      = (const float*)d_in[3];
    const float* Wa      = (const float*)d_in[4];
    const float* Wb      = (const float*)d_in[5];
    const float* Wg      = (const float*)d_in[6];
    const float* Wo      = (const float*)d_in[7];
    const float* A_log   = (const float*)d_in[8];
    const float* dt_bias = (const float*)d_in[9];
    const float* conv_q  = (const float*)d_in[10];
    const float* conv_k  = (const float*)d_in[11];
    const float* conv_v  = (const float*)d_in[12];
    const float* o_nw    = (const float*)d_in[13];
    float* out = (float*)d_out;

    float *qpre, *kpre, *vpre, *gatep, *obuf;
    float *apre, *bpre, *alpha, *beta, *wtab;
    __nv_bfloat16 *xh, *xl, *oh, *ol, *wth, *wtl;
    cudaGetSymbolAddress((void**)&qpre,  g_qpre);
    cudaGetSymbolAddress((void**)&kpre,  g_kpre);
    cudaGetSymbolAddress((void**)&vpre,  g_vpre);
    cudaGetSymbolAddress((void**)&gatep, g_gate);
    cudaGetSymbolAddress((void**)&obuf,  g_o);
    cudaGetSymbolAddress((void**)&apre,  g_apre);
    cudaGetSymbolAddress((void**)&bpre,  g_bpre);
    cudaGetSymbolAddress((void**)&alpha, g_alpha);
    cudaGetSymbolAddress((void**)&beta,  g_beta);
    cudaGetSymbolAddress((void**)&wtab,  g_wtab);
    cudaGetSymbolAddress((void**)&xh,    g_xh);
    cudaGetSymbolAddress((void**)&xl,    g_xl);
    cudaGetSymbolAddress((void**)&oh,    g_oh);
    cudaGetSymbolAddress((void**)&ol,    g_ol);
    cudaGetSymbolAddress((void**)&wth,   g_wth);
    cudaGetSymbolAddress((void**)&wtl,   g_wtl);
    float *q, *k, *v;
    cudaGetSymbolAddress((void**)&q, g_q);
    cudaGetSymbolAddress((void**)&k, g_k);
    cudaGetSymbolAddress((void**)&v, g_v);

    cudaFuncSetAttribute(gemm_mma<0>, cudaFuncAttributeMaxDynamicSharedMemorySize,
                         GEMM_SMEM);
    cudaFuncSetAttribute(gemm_mma<1>, cudaFuncAttributeMaxDynamicSharedMemorySize,
                         GEMM_SMEM);
    cudaFuncSetAttribute(scan_kernel, cudaFuncAttributeMaxDynamicSharedMemorySize,
                         SCAN_SMEM);

    dim3 tb(32, 8);

    // 1) split x into bf16 hi/lo
    cvt_hilo<<<(NTOK*ND + 255)/256, 256>>>(x, xh, xl, NTOK*ND);
    // 2) all 4 projection weight transposes in one launch
    transpose_all<<<6144, tb>>>(Wq, Wk, Wv, Wg, wth, wtl);
    // 3) Wa|Wb transpose table
    build_wtab<<<(16*ND + 255)/256, 256>>>(Wa, Wb, wtab);
    // 4) fused projection GEMM  <-- ncu capture slot
    gemm_mma<1><<<dim3(NPROJ/128, NTOK/128), 256, GEMM_SMEM>>>(
        xh, xl, wth, wtl, qpre, kpre, vpre, gatep, 0, ND);

    // Wa/Wb small-N projection
    abproj_kernel<<<(NTOK*32 + 255)/256, 256>>>(x, wtab, apre, bpre);
    ab_kernel<<<(NTOK*NH + 255)/256, 256>>>(apre, bpre, A_log, dt_bias, alpha, beta);

    conv_silu_kernel<KEYDIM, true ><<<NTOK, KEYDIM/4>>>(qpre, conv_q, q);
    conv_silu_kernel<KEYDIM, true ><<<NTOK, KEYDIM/4>>>(kpre, conv_k, k);
    conv_silu_kernel<VALDIM, false><<<NTOK, VALDIM/4>>>(vpre, conv_v, v);

    scan_kernel<<<NB*NH*8, 256, SCAN_SMEM>>>();

    gate_kernel<<<NTOK*NH, VDIM>>>(obuf, gatep, o_nw, oh, ol);

    // Output projection
    transpose_cvt<<<dim3(ND/32, VALDIM/32), tb>>>(Wo, wth, wtl, VALDIM, ND);
    gemm_mma<0><<<dim3(ND/128, NTOK/128), 256, GEMM_SMEM>>>(
        oh, ol, wth, wtl, out, nullptr, nullptr, nullptr, ND, VALDIM);
}